// round 10
// baseline (speedup 1.0000x reference)
#include <cuda_runtime.h>

// PrototypeLoss: mean_i || features[i] - prototypes[labels[i]] ||^2
// N=131072, D=512, C=1000. features f32 [N,D], labels int32 OR int64 [N]
// (detected per-block at runtime), prototypes f32 [C,D]. Output f32 [1,1].
//
// R6 finding: 8192 small blocks -> per-block overhead (detect-latency prologue
// + reduce/atomic tail) ~ equal to per-block streaming work -> DRAM only 58%.
// R7 design (4th submit; prior three hit broker timeouts): 1024 blocks, 16
// samples/warp looped, labels prefetched via shuffle, __ldcs streaming feature
// loads. Fused detect + last-block finalize (graph-replay safe).

#define N_SAMPLES 131072
#define DIM 512
#define NUM_CLASSES 1000
#define WARPS_PER_BLOCK 8
#define SAMPLES_PER_WARP 16
#define NUM_BLOCKS (N_SAMPLES / (WARPS_PER_BLOCK * SAMPLES_PER_WARP))  // 1024

__device__ double g_acc;            // zero at module load; reset by last block
__device__ unsigned int g_count;    // zero at module load; reset by last block

__device__ __forceinline__ float4 ldcs4(const float4* p) {
    return __ldcs(p);   // evict-first streaming load (features read once)
}

__device__ __forceinline__ float sample_pair_dist2(
    const float* __restrict__ feat, const float* __restrict__ protos,
    int s0, int lab0, int lab1, int lane)
{
    const float4* f0 = (const float4*)(feat + (size_t)s0 * DIM);
    const float4* f1 = (const float4*)(feat + (size_t)(s0 + 1) * DIM);
    const float4* p0 = (const float4*)(protos + (size_t)lab0 * DIM);
    const float4* p1 = (const float4*)(protos + (size_t)lab1 * DIM);

    // 16 front-batched wide loads; each a fully coalesced 512B warp txn.
    float4 a0 = ldcs4(f0 + lane +  0);
    float4 a1 = ldcs4(f0 + lane + 32);
    float4 a2 = ldcs4(f0 + lane + 64);
    float4 a3 = ldcs4(f0 + lane + 96);
    float4 a4 = ldcs4(f1 + lane +  0);
    float4 a5 = ldcs4(f1 + lane + 32);
    float4 a6 = ldcs4(f1 + lane + 64);
    float4 a7 = ldcs4(f1 + lane + 96);
    float4 b0 = p0[lane +  0];
    float4 b1 = p0[lane + 32];
    float4 b2 = p0[lane + 64];
    float4 b3 = p0[lane + 96];
    float4 b4 = p1[lane +  0];
    float4 b5 = p1[lane + 32];
    float4 b6 = p1[lane + 64];
    float4 b7 = p1[lane + 96];

    float s = 0.0f, d;
    d = a0.x - b0.x; s = fmaf(d, d, s);
    d = a0.y - b0.y; s = fmaf(d, d, s);
    d = a0.z - b0.z; s = fmaf(d, d, s);
    d = a0.w - b0.w; s = fmaf(d, d, s);
    d = a1.x - b1.x; s = fmaf(d, d, s);
    d = a1.y - b1.y; s = fmaf(d, d, s);
    d = a1.z - b1.z; s = fmaf(d, d, s);
    d = a1.w - b1.w; s = fmaf(d, d, s);
    d = a2.x - b2.x; s = fmaf(d, d, s);
    d = a2.y - b2.y; s = fmaf(d, d, s);
    d = a2.z - b2.z; s = fmaf(d, d, s);
    d = a2.w - b2.w; s = fmaf(d, d, s);
    d = a3.x - b3.x; s = fmaf(d, d, s);
    d = a3.y - b3.y; s = fmaf(d, d, s);
    d = a3.z - b3.z; s = fmaf(d, d, s);
    d = a3.w - b3.w; s = fmaf(d, d, s);
    d = a4.x - b4.x; s = fmaf(d, d, s);
    d = a4.y - b4.y; s = fmaf(d, d, s);
    d = a4.z - b4.z; s = fmaf(d, d, s);
    d = a4.w - b4.w; s = fmaf(d, d, s);
    d = a5.x - b5.x; s = fmaf(d, d, s);
    d = a5.y - b5.y; s = fmaf(d, d, s);
    d = a5.z - b5.z; s = fmaf(d, d, s);
    d = a5.w - b5.w; s = fmaf(d, d, s);
    d = a6.x - b6.x; s = fmaf(d, d, s);
    d = a6.y - b6.y; s = fmaf(d, d, s);
    d = a6.z - b6.z; s = fmaf(d, d, s);
    d = a6.w - b6.w; s = fmaf(d, d, s);
    d = a7.x - b7.x; s = fmaf(d, d, s);
    d = a7.y - b7.y; s = fmaf(d, d, s);
    d = a7.z - b7.z; s = fmaf(d, d, s);
    d = a7.w - b7.w; s = fmaf(d, d, s);
    return s;
}

__global__ __launch_bounds__(256) void proto_loss_fused_kernel(
    const float* __restrict__ feat,
    const void* __restrict__ labels,
    const float* __restrict__ protos,
    float* __restrict__ out)
{
    const int lane = threadIdx.x & 31;
    const int wid  = threadIdx.x >> 5;

    // ---- Label dtype detect (per block, uniform result) ----
    // Odd 32-bit words are int64 hi-words (all 0 since labels<1000) or int32
    // labels of odd samples (P(all 256 zero) ~ 1e-768). 2KB, L2-broadcast.
    const int* li = (const int*)labels;
    int labels_are_i32 = __syncthreads_or(li[2 * threadIdx.x + 1] != 0);

    // ---- Prefetch this warp's 16 labels (lanes 0..15), shuffle later ----
    const int warp_global = blockIdx.x * WARPS_PER_BLOCK + wid;
    const int base = warp_global * SAMPLES_PER_WARP;

    int mylab = 0;
    if (lane < SAMPLES_PER_WARP) {
        long long v = labels_are_i32
            ? (long long)li[base + lane]
            : ((const long long*)labels)[base + lane];
        // Defensive clamp: never OOB into prototypes.
        if (v < 0) v = 0;
        if (v >= NUM_CLASSES) v = NUM_CLASSES - 1;
        mylab = (int)v;
    }

    float s = 0.0f;
    #pragma unroll
    for (int it = 0; it < SAMPLES_PER_WARP / 2; it++) {
        int lab0 = __shfl_sync(0xffffffffu, mylab, 2 * it);
        int lab1 = __shfl_sync(0xffffffffu, mylab, 2 * it + 1);
        s += sample_pair_dist2(feat, protos, base + 2 * it, lab0, lab1, lane);
    }

    // ---- Warp reduce ----
    #pragma unroll
    for (int o = 16; o > 0; o >>= 1)
        s += __shfl_xor_sync(0xffffffffu, s, o);

    // ---- Block reduce ----
    __shared__ float warp_sums[WARPS_PER_BLOCK];
    __shared__ bool is_last;
    if (lane == 0) warp_sums[wid] = s;
    __syncthreads();

    if (threadIdx.x == 0) {
        float t = 0.0f;
        #pragma unroll
        for (int i = 0; i < WARPS_PER_BLOCK; i++) t += warp_sums[i];
        atomicAdd(&g_acc, (double)t);
        __threadfence();
        unsigned int done = atomicAdd(&g_count, 1u);
        is_last = (done == (unsigned int)(gridDim.x - 1));
    }
    __syncthreads();

    // ---- Last-block finalize + reset (keeps graph replays correct) ----
    if (is_last && threadIdx.x == 0) {
        double total = *((volatile double*)&g_acc);
        out[0] = (float)(total / (double)N_SAMPLES);
        g_acc = 0.0;
        g_count = 0u;
        __threadfence();
    }
}

extern "C" void kernel_launch(void* const* d_in, const int* in_sizes, int n_in,
                              void* d_out, int out_size) {
    const float* feat   = (const float*)d_in[0];
    const void*  labels = d_in[1];
    const float* protos = (const float*)d_in[2];
    float* out = (float*)d_out;

    proto_loss_fused_kernel<<<NUM_BLOCKS, WARPS_PER_BLOCK * 32>>>(
        feat, labels, protos, out);
}